// round 2
// baseline (speedup 1.0000x reference)
#include <cuda_runtime.h>

#define NN 512          // total nodes
#define FF 512          // feature dim
#define HH 512          // hidden dim
#define RR 4            // relations
#define LN_EPS 1e-5f
#define THRESH 0.2f

// Scratch (device globals: no allocation allowed in kernel_launch)
__device__ float g_a[RR][NN][HH];   // x @ Wl[r]^T + b1[r]
__device__ float g_b[RR][NN][HH];   // x @ Wr[r]^T

// ---------------------------------------------------------------------------
// Kernel 0: concat feats_img/feats_txt into out[0 : NN*FF]  (x output + GEMM src)
// ---------------------------------------------------------------------------
__global__ void concat_kernel(const float* __restrict__ img,
                              const float* __restrict__ txt,
                              float* __restrict__ out) {
    int idx = blockIdx.x * blockDim.x + threadIdx.x;   // float4 index
    const int HALF = 256 * FF / 4;                     // 32768 float4 per half
    float4 v;
    if (idx < HALF) v = reinterpret_cast<const float4*>(img)[idx];
    else            v = reinterpret_cast<const float4*>(txt)[idx - HALF];
    reinterpret_cast<float4*>(out)[idx] = v;
}

// ---------------------------------------------------------------------------
// Kernel 1: SGEMM  (BM=BN=128, BK=8, 8x8 per thread, 256 threads)
// Computes g_a[r] (side 0, +b1) and g_b[r] (side 1) for z = r*2+side.
// A = x [NN,FF] row-major; B = W1[r,:,side*FF + f] rows stride 2*FF.
// ---------------------------------------------------------------------------
__global__ __launch_bounds__(256) void gemm_ab(const float* __restrict__ x,
                                               const float* __restrict__ W1,
                                               const float* __restrict__ b1) {
    const int r    = blockIdx.z >> 1;
    const int side = blockIdx.z & 1;
    const float* B = W1 + (size_t)r * HH * (2 * FF) + side * FF;
    float* out = side ? &g_b[r][0][0] : &g_a[r][0][0];

    const int bi = blockIdx.y * 128;   // node-row block
    const int bh = blockIdx.x * 128;   // hidden-col block

    __shared__ float As[8][128];
    __shared__ float Bs[8][128];

    const int tid  = threadIdx.x;
    const int lrow = tid >> 1;            // 0..127
    const int lcol = (tid & 1) << 2;      // 0 or 4
    const int ty   = tid >> 4;            // 0..15
    const int tx   = tid & 15;            // 0..15

    float acc[8][8];
#pragma unroll
    for (int m = 0; m < 8; m++)
#pragma unroll
        for (int n = 0; n < 8; n++) acc[m][n] = 0.f;

    for (int k0 = 0; k0 < FF; k0 += 8) {
        float4 av = *reinterpret_cast<const float4*>(x + (size_t)(bi + lrow) * FF + k0 + lcol);
        float4 bv = *reinterpret_cast<const float4*>(B + (size_t)(bh + lrow) * (2 * FF) + k0 + lcol);
        As[lcol + 0][lrow] = av.x; As[lcol + 1][lrow] = av.y;
        As[lcol + 2][lrow] = av.z; As[lcol + 3][lrow] = av.w;
        Bs[lcol + 0][lrow] = bv.x; Bs[lcol + 1][lrow] = bv.y;
        Bs[lcol + 2][lrow] = bv.z; Bs[lcol + 3][lrow] = bv.w;
        __syncthreads();
#pragma unroll
        for (int kk = 0; kk < 8; kk++) {
            float ra[8], rb[8];
#pragma unroll
            for (int m = 0; m < 8; m++) ra[m] = As[kk][ty * 8 + m];
#pragma unroll
            for (int n = 0; n < 8; n++) rb[n] = Bs[kk][tx * 8 + n];
#pragma unroll
            for (int m = 0; m < 8; m++)
#pragma unroll
                for (int n = 0; n < 8; n++) acc[m][n] = fmaf(ra[m], rb[n], acc[m][n]);
        }
        __syncthreads();
    }

#pragma unroll
    for (int n = 0; n < 8; n++) {
        int h = bh + tx * 8 + n;
        float bias = side ? 0.f : b1[r * HH + h];
#pragma unroll
        for (int m = 0; m < 8; m++) {
            out[(size_t)(bi + ty * 8 + m) * HH + h] = acc[m][n] + bias;
        }
    }
}

// ---------------------------------------------------------------------------
// Kernel 2: pairwise LN-MLP + argmax over relations.
// Block = 256 thr = 8 warps. Tile: 4 i-rows (smem) x 8 j-cols (one j/warp).
// For each (i,j,r): h = a_i + b_j (b1 folded into a), layernorm over H=512,
// relu, dot w2, +b2; track max/argmax over r with first-occurrence ties.
// ---------------------------------------------------------------------------
#define ITILE 4

__global__ __launch_bounds__(256) void pairwise_kernel(
        const float* __restrict__ gamma, const float* __restrict__ beta,
        const float* __restrict__ w2,    const float* __restrict__ b2,
        float* __restrict__ out) {
    __shared__ float sa[RR][ITILE][HH];   // 32 KB

    const int ig0 = blockIdx.y * ITILE;
    const int jg0 = blockIdx.x * 8;
    const int tid  = threadIdx.x;
    const int warp = tid >> 5;
    const int lane = tid & 31;

    // stage a rows: RR*ITILE*HH = 8192 floats = 2048 float4
    {
        const float4* dst_chk;
        (void)dst_chk;
        for (int t = tid; t < 2048; t += 256) {
            int rr  = t >> 9;          // /512
            int rem = t & 511;
            int ii  = rem >> 7;        // /128
            int c4  = rem & 127;
            reinterpret_cast<float4*>(&sa[rr][ii][0])[c4] =
                reinterpret_cast<const float4*>(&g_a[rr][ig0 + ii][0])[c4];
        }
    }
    __syncthreads();

    const int j = jg0 + warp;

    float best[ITILE];
    int   barg[ITILE];
#pragma unroll
    for (int i = 0; i < ITILE; i++) { best[i] = -1e30f; barg[i] = 0; }

#pragma unroll 1
    for (int r = 0; r < RR; r++) {
        float bb[16], gg[16], be[16], ww[16];
#pragma unroll
        for (int q = 0; q < 16; q++) {
            int h = q * 32 + lane;
            bb[q] = g_b[r][j][h];
            gg[q] = gamma[r * HH + h];
            be[q] = beta[r * HH + h];
            ww[q] = w2[r * HH + h];
        }
        float bias2 = b2[r];

#pragma unroll
        for (int i = 0; i < ITILE; i++) {
            float h16[16];
            float s = 0.f, s2 = 0.f;
#pragma unroll
            for (int q = 0; q < 16; q++) {
                float hv = sa[r][i][q * 32 + lane] + bb[q];
                h16[q] = hv;
                s  += hv;
                s2  = fmaf(hv, hv, s2);
            }
#pragma unroll
            for (int o = 16; o > 0; o >>= 1) {
                s  += __shfl_xor_sync(0xffffffffu, s,  o);
                s2 += __shfl_xor_sync(0xffffffffu, s2, o);
            }
            float mu   = s * (1.f / (float)HH);
            float var  = fmaf(-mu, mu, s2 * (1.f / (float)HH));
            float rstd = rsqrtf(var + LN_EPS);
            float nmr  = -mu * rstd;
            float dot = 0.f;
#pragma unroll
            for (int q = 0; q < 16; q++) {
                float t  = fmaf(h16[q], rstd, nmr);
                float hn = fmaf(t, gg[q], be[q]);
                hn = fmaxf(hn, 0.f);
                dot = fmaf(hn, ww[q], dot);
            }
#pragma unroll
            for (int o = 16; o > 0; o >>= 1)
                dot += __shfl_xor_sync(0xffffffffu, dot, o);
            float sc = dot + bias2;
            if (sc > best[i]) { best[i] = sc; barg[i] = r; }
        }
    }

    // Output layout (float32): [x | best_score | best_rel | edge_mask]
    float* oscore = out + NN * FF;
    float* orel   = oscore + NN * NN;
    float* omask  = orel + NN * NN;
#pragma unroll
    for (int i = 0; i < ITILE; i++) {
        if (lane == i) {
            int gi = ig0 + i;
            size_t idx = (size_t)gi * NN + j;
            oscore[idx] = best[i];
            orel[idx]   = (float)barg[i];
            omask[idx]  = (gi != j && best[i] > THRESH) ? 1.f : 0.f;
        }
    }
}

// ---------------------------------------------------------------------------
// launch
// inputs: 0 feats_img [256,512] f32, 1 feats_txt [256,512] f32,
//         2 W1 [4,512,1024] f32, 3 b1 [4,512] f32, 4 gamma [4,512] f32,
//         5 beta [4,512] f32, 6 w2 [4,512] f32, 7 b2 [4] f32
// out: float32, 4*262144 = 1048576 elems: x, best_score, best_rel, edge_mask
// ---------------------------------------------------------------------------
extern "C" void kernel_launch(void* const* d_in, const int* in_sizes, int n_in,
                              void* d_out, int out_size) {
    const float* img   = (const float*)d_in[0];
    const float* txt   = (const float*)d_in[1];
    const float* W1    = (const float*)d_in[2];
    const float* b1    = (const float*)d_in[3];
    const float* gamma = (const float*)d_in[4];
    const float* beta  = (const float*)d_in[5];
    const float* w2    = (const float*)d_in[6];
    const float* b2    = (const float*)d_in[7];
    float* out = (float*)d_out;

    // x -> out[0 : 512*512]  (also used as GEMM input)
    concat_kernel<<<(NN * FF / 4 + 255) / 256, 256>>>(img, txt, out);

    // projections: grid (h-blocks, i-blocks, r*2+side) = (4,4,8) = 128 blocks
    dim3 ggrid(HH / 128, NN / 128, RR * 2);
    gemm_ab<<<ggrid, 256>>>(out, W1, b1);

    // pairwise: grid (j-groups of 8, i-groups of ITILE)
    dim3 pgrid(NN / 8, NN / ITILE);
    pairwise_kernel<<<pgrid, 256>>>(gamma, beta, w2, b2, out);
}

// round 3
// speedup vs baseline: 1.3322x; 1.3322x over previous
#include <cuda_runtime.h>

#define NN 512          // total nodes
#define FF 512          // feature dim
#define HH 512          // hidden dim
#define RR 4            // relations
#define LN_EPS 1e-5f
#define THRESH 0.2f

typedef unsigned long long ull;

// Scratch (device globals: no allocation allowed in kernel_launch)
__device__ float g_a[RR][NN][HH];   // x @ Wl[r]^T + b1[r]
__device__ float g_b[RR][NN][HH];   // x @ Wr[r]^T
__device__ float g_sa[RR][NN];      // row sums of g_a
__device__ float g_sb[RR][NN];      // row sums of g_b

// ---------------------------------------------------------------------------
// packed f32x2 helpers (Blackwell sm_103a: FFMA2 only reachable via PTX)
// ---------------------------------------------------------------------------
__device__ __forceinline__ ull add2(ull a, ull b) {
    ull d; asm("add.rn.f32x2 %0,%1,%2;" : "=l"(d) : "l"(a), "l"(b)); return d;
}
__device__ __forceinline__ ull fma2(ull a, ull b, ull c) {
    ull d; asm("fma.rn.f32x2 %0,%1,%2,%3;" : "=l"(d) : "l"(a), "l"(b), "l"(c)); return d;
}
__device__ __forceinline__ ull bcast2(float x) {
    ull d; unsigned u = __float_as_uint(x);
    asm("mov.b64 %0,{%1,%1};" : "=l"(d) : "r"(u)); return d;
}
__device__ __forceinline__ float sum2(ull v) {
    unsigned lo, hi;
    asm("mov.b64 {%0,%1},%2;" : "=r"(lo), "=r"(hi) : "l"(v));
    return __uint_as_float(lo) + __uint_as_float(hi);
}
__device__ __forceinline__ ull relu2(ull v) {
    unsigned lo, hi;
    asm("mov.b64 {%0,%1},%2;" : "=r"(lo), "=r"(hi) : "l"(v));
    float flo = fmaxf(__uint_as_float(lo), 0.f);
    float fhi = fmaxf(__uint_as_float(hi), 0.f);
    ull d;
    asm("mov.b64 %0,{%1,%2};" : "=l"(d) : "r"(__float_as_uint(flo)), "r"(__float_as_uint(fhi)));
    return d;
}

// ---------------------------------------------------------------------------
// Kernel 0: concat feats_img/feats_txt into out[0 : NN*FF]
// ---------------------------------------------------------------------------
__global__ void concat_kernel(const float* __restrict__ img,
                              const float* __restrict__ txt,
                              float* __restrict__ out) {
    int idx = blockIdx.x * blockDim.x + threadIdx.x;
    const int HALF = 256 * FF / 4;
    float4 v;
    if (idx < HALF) v = reinterpret_cast<const float4*>(img)[idx];
    else            v = reinterpret_cast<const float4*>(txt)[idx - HALF];
    reinterpret_cast<float4*>(out)[idx] = v;
}

// ---------------------------------------------------------------------------
// Kernel 1: SGEMM (BM=BN=128, BK=8, 8x8/thread) with packed f32x2 inner loop.
// z = r*2+side: side 0 -> g_a (+b1), side 1 -> g_b.
// ---------------------------------------------------------------------------
__global__ __launch_bounds__(256) void gemm_ab(const float* __restrict__ x,
                                               const float* __restrict__ W1,
                                               const float* __restrict__ b1) {
    const int r    = blockIdx.z >> 1;
    const int side = blockIdx.z & 1;
    const float* B = W1 + (size_t)r * HH * (2 * FF) + side * FF;
    float* outp = side ? &g_b[r][0][0] : &g_a[r][0][0];

    const int bi = blockIdx.y * 128;
    const int bh = blockIdx.x * 128;

    __shared__ __align__(16) float As[8][128];
    __shared__ __align__(16) float Bs[8][128];

    const int tid  = threadIdx.x;
    const int lrow = tid >> 1;
    const int lcol = (tid & 1) << 2;
    const int ty   = tid >> 4;
    const int tx   = tid & 15;

    ull acc2[8][4];
#pragma unroll
    for (int m = 0; m < 8; m++)
#pragma unroll
        for (int n = 0; n < 4; n++) acc2[m][n] = 0ull;

    for (int k0 = 0; k0 < FF; k0 += 8) {
        float4 av = *reinterpret_cast<const float4*>(x + (size_t)(bi + lrow) * FF + k0 + lcol);
        float4 bv = *reinterpret_cast<const float4*>(B + (size_t)(bh + lrow) * (2 * FF) + k0 + lcol);
        As[lcol + 0][lrow] = av.x; As[lcol + 1][lrow] = av.y;
        As[lcol + 2][lrow] = av.z; As[lcol + 3][lrow] = av.w;
        Bs[lcol + 0][lrow] = bv.x; Bs[lcol + 1][lrow] = bv.y;
        Bs[lcol + 2][lrow] = bv.z; Bs[lcol + 3][lrow] = bv.w;
        __syncthreads();
#pragma unroll
        for (int kk = 0; kk < 8; kk++) {
            float4 a0 = *reinterpret_cast<const float4*>(&As[kk][ty * 8]);
            float4 a1 = *reinterpret_cast<const float4*>(&As[kk][ty * 8 + 4]);
            ulonglong2 b0 = *reinterpret_cast<const ulonglong2*>(&Bs[kk][tx * 8]);
            ulonglong2 b1v = *reinterpret_cast<const ulonglong2*>(&Bs[kk][tx * 8 + 4]);
            ull rb2[4] = {b0.x, b0.y, b1v.x, b1v.y};
            float ra[8] = {a0.x, a0.y, a0.z, a0.w, a1.x, a1.y, a1.z, a1.w};
#pragma unroll
            for (int m = 0; m < 8; m++) {
                ull ra2 = bcast2(ra[m]);
#pragma unroll
                for (int n = 0; n < 4; n++)
                    acc2[m][n] = fma2(ra2, rb2[n], acc2[m][n]);
            }
        }
        __syncthreads();
    }

    // epilogue: +bias (side 0), packed 64-bit stores
    ull bias2[4];
    if (side) {
#pragma unroll
        for (int n = 0; n < 4; n++) bias2[n] = 0ull;
    } else {
        const ull* bp = reinterpret_cast<const ull*>(b1 + r * HH + bh + tx * 8);
#pragma unroll
        for (int n = 0; n < 4; n++) bias2[n] = bp[n];
    }
#pragma unroll
    for (int m = 0; m < 8; m++) {
        ull* orow = reinterpret_cast<ull*>(outp + (size_t)(bi + ty * 8 + m) * HH + bh + tx * 8);
#pragma unroll
        for (int n = 0; n < 4; n++)
            orow[n] = add2(acc2[m][n], bias2[n]);
    }
}

// ---------------------------------------------------------------------------
// Kernel 1b: row sums of g_a / g_b (one warp per row).
// ---------------------------------------------------------------------------
__global__ __launch_bounds__(256) void rowsum_kernel() {
    int gw   = (blockIdx.x * 256 + threadIdx.x) >> 5;   // global warp id, 0..4095
    int lane = threadIdx.x & 31;
    int side = gw >> 11;            // 0: a, 1: b
    int rem  = gw & 2047;
    const float* base = side ? &g_b[0][0][0] : &g_a[0][0][0];
    const float* row  = base + (size_t)rem * HH;        // rem = r*NN + node

    float s = 0.f;
#pragma unroll
    for (int c = 0; c < 4; c++) {
        float4 v = *reinterpret_cast<const float4*>(row + c * 128 + lane * 4);
        s += (v.x + v.y) + (v.z + v.w);
    }
#pragma unroll
    for (int o = 16; o > 0; o >>= 1) s += __shfl_xor_sync(0xffffffffu, s, o);
    if (lane == 0) {
        float* dst = side ? &g_sb[0][0] : &g_sa[0][0];
        dst[rem] = s;
    }
}

// ---------------------------------------------------------------------------
// Kernel 2: pairwise LN-MLP + argmax, packed f32x2.
// Block: 256 thr (8 warps). Tile: BI=16 i-rows (smem) x 8 j (one per warp).
// Lane L keeps best score/rel for i=L (L<BI) as registers (butterfly bcast).
// h mapping per lane: elements c*128 + lane*4 + {0..3}, c=0..3 (16 elems).
// ---------------------------------------------------------------------------
#define BI 16

__global__ __launch_bounds__(256) void pairwise_kernel(
        const float* __restrict__ gamma, const float* __restrict__ beta,
        const float* __restrict__ w2,    const float* __restrict__ b2,
        float* __restrict__ out) {
    __shared__ __align__(16) float sa[BI][HH];   // 32 KB
    __shared__ float sSA[BI];

    const int ig0  = blockIdx.y * BI;
    const int tid  = threadIdx.x;
    const int warp = tid >> 5;
    const int lane = tid & 31;
    const int j    = blockIdx.x * 8 + warp;

    float bestv = -1e30f;
    int   bestr = 0;

    const float inv_h = 1.f / (float)HH;

#pragma unroll 1
    for (int r = 0; r < RR; r++) {
        __syncthreads();
        // stage a rows for this r: BI*HH = 8192 floats = 2048 float4
        for (int t = tid; t < BI * HH / 4; t += 256) {
            int row = t >> 7;
            int c4  = t & 127;
            reinterpret_cast<float4*>(&sa[row][0])[c4] =
                reinterpret_cast<const float4*>(&g_a[r][ig0 + row][0])[c4];
        }
        if (tid < BI) sSA[tid] = g_sa[r][ig0 + tid];
        __syncthreads();

        // per-warp register-resident slices (packed pairs)
        ull bb[8], gg[8], be[8], ww[8];
#pragma unroll
        for (int c = 0; c < 4; c++) {
            int off = r * HH + c * 128 + lane * 4;
            ulonglong2 vb = *reinterpret_cast<const ulonglong2*>(&g_b[r][j][c * 128 + lane * 4]);
            bb[2 * c] = vb.x; bb[2 * c + 1] = vb.y;
            ulonglong2 vg = *reinterpret_cast<const ulonglong2*>(gamma + off);
            gg[2 * c] = vg.x; gg[2 * c + 1] = vg.y;
            ulonglong2 ve = *reinterpret_cast<const ulonglong2*>(beta + off);
            be[2 * c] = ve.x; be[2 * c + 1] = ve.y;
            ulonglong2 vw = *reinterpret_cast<const ulonglong2*>(w2 + off);
            ww[2 * c] = vw.x; ww[2 * c + 1] = vw.y;
        }
        float SB = g_sb[r][j];
        float bias2 = b2[r];

#pragma unroll 1
        for (int ii = 0; ii < BI / 2; ii++) {
            const int i0 = 2 * ii, i1 = 2 * ii + 1;
            const ulonglong2* pa0 = reinterpret_cast<const ulonglong2*>(&sa[i0][0]);
            const ulonglong2* pa1 = reinterpret_cast<const ulonglong2*>(&sa[i1][0]);

            ull h0[8], h1[8];
            ull q0 = 0ull, q1 = 0ull;
#pragma unroll
            for (int c = 0; c < 4; c++) {
                ulonglong2 a0 = pa0[c * 32 + lane];
                ulonglong2 a1 = pa1[c * 32 + lane];
                h0[2 * c]     = add2(a0.x, bb[2 * c]);
                h0[2 * c + 1] = add2(a0.y, bb[2 * c + 1]);
                h1[2 * c]     = add2(a1.x, bb[2 * c]);
                h1[2 * c + 1] = add2(a1.y, bb[2 * c + 1]);
                q0 = fma2(h0[2 * c], h0[2 * c], q0);
                q0 = fma2(h0[2 * c + 1], h0[2 * c + 1], q0);
                q1 = fma2(h1[2 * c], h1[2 * c], q1);
                q1 = fma2(h1[2 * c + 1], h1[2 * c + 1], q1);
            }
            float s20 = sum2(q0);
            float s21 = sum2(q1);
#pragma unroll
            for (int o = 16; o > 0; o >>= 1) {
                s20 += __shfl_xor_sync(0xffffffffu, s20, o);
                s21 += __shfl_xor_sync(0xffffffffu, s21, o);
            }
            float mu0 = (sSA[i0] + SB) * inv_h;
            float mu1 = (sSA[i1] + SB) * inv_h;
            float var0 = fmaf(-mu0, mu0, s20 * inv_h);
            float var1 = fmaf(-mu1, mu1, s21 * inv_h);
            float rstd0 = rsqrtf(var0 + LN_EPS);
            float rstd1 = rsqrtf(var1 + LN_EPS);
            ull r20 = bcast2(rstd0), n20 = bcast2(-mu0 * rstd0);
            ull r21 = bcast2(rstd1), n21 = bcast2(-mu1 * rstd1);

            ull d0 = 0ull, d1 = 0ull;
#pragma unroll
            for (int q = 0; q < 8; q++) {
                ull t0 = fma2(h0[q], r20, n20);
                ull t1 = fma2(h1[q], r21, n21);
                t0 = fma2(t0, gg[q], be[q]);
                t1 = fma2(t1, gg[q], be[q]);
                t0 = relu2(t0);
                t1 = relu2(t1);
                d0 = fma2(t0, ww[q], d0);
                d1 = fma2(t1, ww[q], d1);
            }
            float dot0 = sum2(d0);
            float dot1 = sum2(d1);
#pragma unroll
            for (int o = 16; o > 0; o >>= 1) {
                dot0 += __shfl_xor_sync(0xffffffffu, dot0, o);
                dot1 += __shfl_xor_sync(0xffffffffu, dot1, o);
            }
            float sc0 = dot0 + bias2;
            float sc1 = dot1 + bias2;
            if (lane == i0 && sc0 > bestv) { bestv = sc0; bestr = r; }
            if (lane == i1 && sc1 > bestv) { bestv = sc1; bestr = r; }
        }
    }

    // Output layout (float32): [x | best_score | best_rel | edge_mask]
    float* oscore = out + NN * FF;
    float* orel   = oscore + NN * NN;
    float* omask  = orel + NN * NN;
    if (lane < BI) {
        int gi = ig0 + lane;
        size_t idx = (size_t)gi * NN + j;
        oscore[idx] = bestv;
        orel[idx]   = (float)bestr;
        omask[idx]  = (gi != j && bestv > THRESH) ? 1.f : 0.f;
    }
}

// ---------------------------------------------------------------------------
// launch
// ---------------------------------------------------------------------------
extern "C" void kernel_launch(void* const* d_in, const int* in_sizes, int n_in,
                              void* d_out, int out_size) {
    const float* img   = (const float*)d_in[0];
    const float* txt   = (const float*)d_in[1];
    const float* W1    = (const float*)d_in[2];
    const float* b1    = (const float*)d_in[3];
    const float* gamma = (const float*)d_in[4];
    const float* beta  = (const float*)d_in[5];
    const float* w2    = (const float*)d_in[6];
    const float* b2    = (const float*)d_in[7];
    float* out = (float*)d_out;

    concat_kernel<<<(NN * FF / 4 + 255) / 256, 256>>>(img, txt, out);

    dim3 ggrid(HH / 128, NN / 128, RR * 2);
    gemm_ab<<<ggrid, 256>>>(out, W1, b1);

    rowsum_kernel<<<RR * NN * 2 * 32 / 256, 256>>>();

    dim3 pgrid(NN / 8, NN / BI);
    pairwise_kernel<<<pgrid, 256>>>(gamma, beta, w2, b2, out);
}